// round 15
// baseline (speedup 1.0000x reference)
#include <cuda_runtime.h>
#include <cuda_fp16.h>
#include <cstdint>
#include <math.h>

// ---------------------------------------------------------------------------
// STGN_LSTM == pointwise map of X[:,4,:].
// r14 design (z-GEMM on tensor pipe via mma.sync.m16n8k8), r15 fixes the
// misaligned float2 load of (x0,x1) at stride-15 rows (odd rows are 4-mod-8
// aligned) -> three scalar LDG.32 per row.
// Columns paired (zi_u, zT_u): each thread's D fragment holds both gates of
// one unit for rows (g, g+8); epilogue = r13 f32x2 math with lanes = rows.
// ---------------------------------------------------------------------------

typedef unsigned long long u64;

static __device__ __forceinline__ float tanh_mufu(float x) {
    float y; asm("tanh.approx.f32 %0, %1;" : "=f"(y) : "f"(x)); return y;
}
static __device__ __forceinline__ u64 pk(float lo, float hi) {
    u64 r; asm("mov.b64 %0, {%1, %2};" : "=l"(r) : "f"(lo), "f"(hi)); return r;
}
static __device__ __forceinline__ void upk(float& lo, float& hi, u64 v) {
    asm("mov.b64 {%0, %1}, %2;" : "=f"(lo), "=f"(hi) : "l"(v));
}
static __device__ __forceinline__ u64 fma2(u64 a, u64 b, u64 c) {
    u64 d; asm("fma.rn.f32x2 %0, %1, %2, %3;" : "=l"(d) : "l"(a), "l"(b), "l"(c));
    return d;
}
static __device__ __forceinline__ u64 mul2(u64 a, u64 b) {
    u64 d; asm("mul.rn.f32x2 %0, %1, %2;" : "=l"(d) : "l"(a), "l"(b)); return d;
}
static __device__ __forceinline__ u64 tanh2_mufu(u64 v) {
    float a, b; upk(a, b, v);
    return pk(tanh_mufu(a), tanh_mufu(b));
}
static __device__ __forceinline__ u64 clamp2_pm2(u64 v) {
    float a, b; upk(a, b, v);
    a = fminf(fmaxf(a, -2.0f), 2.0f);
    b = fminf(fmaxf(b, -2.0f), 2.0f);
    return pk(a, b);
}
static __device__ __forceinline__ uint32_t packh2(float lo, float hi) {
    __half2 h = __floats2half2_rn(lo, hi);
    return *(const uint32_t*)&h;
}
// D = A(16x8,f16,row) * B(8x8,f16,col) + D   (fp32 accum)
static __device__ __forceinline__ void mma16n8k8(float* d, uint32_t a0, uint32_t a1,
                                                 uint32_t b0) {
    asm volatile(
        "mma.sync.aligned.m16n8k8.row.col.f32.f16.f16.f32 "
        "{%0,%1,%2,%3}, {%4,%5}, {%6}, {%0,%1,%2,%3};"
        : "+f"(d[0]), "+f"(d[1]), "+f"(d[2]), "+f"(d[3])
        : "r"(a0), "r"(a1), "r"(b0));
}

__global__ void __launch_bounds__(128)
stgn_kernel(const float* __restrict__ X,
            const float* __restrict__ Wix, const float* __restrict__ Wix_b,
            const float* __restrict__ Wih_b, const float* __restrict__ bi,
            const float* __restrict__ WTx, const float* __restrict__ WTx_b,
            const float* __restrict__ WTh_b,
            const float* __restrict__ WTt, const float* __restrict__ WTt_b,
            const float* __restrict__ bT,
            const float* __restrict__ clsw, const float* __restrict__ clsb,
            float* __restrict__ out) {
    const int tid  = threadIdx.x;
    const int wid  = tid >> 5;
    const int lane = tid & 31;
    const int g    = lane >> 2;       // row group within 16-row tile
    const int tq   = lane & 3;        // thread-in-group (owns unit 4j+tq in D)

    // ---- one-time: B fragments (W_ext) -------------------------------------
    // B[k][n], n in [0,8): n = 2*(unit within tile) + gate; unit = 4j + (g>>1),
    // gate = g&1. Thread holds k = 2tq, 2tq+1 of column n = g. k>=4 -> 0.
    const int uB   = g >> 1;
    const int gate = g & 1;
    uint32_t bf[16];
#pragma unroll
    for (int j = 0; j < 16; j++) {
        const int u = 4 * j + uB;
        float v0 = 0.0f, v1 = 0.0f;
        if (tq == 0) {
            if (gate == 0) { v0 = 0.5f * Wix[2 * u]; v1 = 0.5f * Wix[2 * u + 1]; }
            else           { v0 = 0.5f * WTx[2 * u]; v1 = 0.5f * WTx[2 * u + 1]; }
        } else if (tq == 1) {
            if (gate == 0) { v1 = 0.5f * (Wih_b[u] + Wix_b[u] + bi[u]); }
            else           { v0 = 0.5f * WTt[u];
                             v1 = 0.5f * (WTh_b[u] + WTx_b[u] + WTt_b[u] + bT[u]); }
        }
        bf[j] = packh2(v0, v1);
    }
    // cls weights for this thread's units (4j + tq), packed for fma2
    u64 clsP[16];
#pragma unroll
    for (int j = 0; j < 16; j++) {
        const float w = clsw[4 * j + tq];
        clsP[j] = pk(w, w);
    }
    const float cb = clsb[0];

    // ---- polynomial constants ----
    // t1 = z*P(z^2), z = clamp(0.5*zi, +-2), s in [0,4]
    const u64 C0 = pk(0.998779f, 0.998779f);
    const u64 C1 = pk(-0.3172255f, -0.3172255f);
    const u64 C2 = pk(0.096472f, 0.096472f);
    const u64 C3 = pk(-0.0181456f, -0.0181456f);
    const u64 C4 = pk(0.0014467f, 0.0014467f);
    // h = tanh(0.5*m), m = uu*(1+t1): m*(A0 + A1 m^2 + A2 m^4)
    const u64 A0 = pk(0.4997350f, 0.4997350f);
    const u64 A1 = pk(-0.0397625f, -0.0397625f);
    const u64 A2 = pk(0.0025309f, 0.0025309f);

    // ---- 4 passes of 16 rows per warp ----
    const size_t warpRow = ((size_t)blockIdx.x * 4 + wid) * 64;

#pragma unroll 1
    for (int ps = 0; ps < 4; ps++) {
        const size_t rg  = warpRow + (size_t)(ps * 16 + g);
        const size_t rg8 = rg + 8;

        // scalar loads: stride-15 rows are not 8B-aligned for odd rows
        const float* pg  = X + rg * 15 + 12;
        const float* pg8 = X + rg8 * 15 + 12;
        const float x0g = pg[0],  x1g = pg[1],  dtg  = pg[2];
        const float x0h = pg8[0], x1h = pg8[1], dtg8 = pg8[2];

        // A fragment: rows g/g+8, k = 2tq,2tq+1 of [x0,x1,dt,1,0...]
        const uint32_t axy_g  = packh2(x0g, x1g);
        const uint32_t adt_g  = packh2(dtg, 1.0f);
        const uint32_t axy_g8 = packh2(x0h, x1h);
        const uint32_t adt_g8 = packh2(dtg8, 1.0f);
        const uint32_t a0 = (tq == 0) ? axy_g  : (tq == 1) ? adt_g  : 0u;
        const uint32_t a1 = (tq == 0) ? axy_g8 : (tq == 1) ? adt_g8 : 0u;

        const u64 dhP = pk(0.5f * dtg, 0.5f * dtg8);
        u64 lgP = pk(0.0f, 0.0f);

#pragma unroll
        for (int j = 0; j < 16; j++) {
            float d[4] = {0.0f, 0.0f, 0.0f, 0.0f};
            mma16n8k8(d, a0, a1, bf[j]);                 // tensor pipe
            const u64 ziP = pk(d[0], d[2]);              // 0.5*zi rows (g,g+8)
            const u64 zTP = pk(d[1], d[3]);              // 0.5*zT

            const u64 t2 = tanh2_mufu(zTP);              // MUFU
            const u64 zc = clamp2_pm2(ziP);              // ALU
            const u64 sz = mul2(zc, zc);
            u64 pq = fma2(C4, sz, C3);
            pq = fma2(pq, sz, C2);
            pq = fma2(pq, sz, C1);
            pq = fma2(pq, sz, C0);
            const u64 t1 = mul2(pq, zc);                 // tanh(0.5 zi) on FMA
            const u64 ta = fma2(t2, dhP, dhP);           // sig(zT)*dt
            const u64 uu = tanh2_mufu(ta);               // MUFU
            const u64 m  = fma2(t1, uu, uu);             // 2*cc
            const u64 sm = mul2(m, m);
            u64 q = fma2(A2, sm, A1);
            q = fma2(q, sm, A0);
            lgP = fma2(mul2(q, m), clsP[j], lgP);        // h = q*m
        }

        // reduce logits across the tq quad (units are split over tq lanes)
        float lg0, lg1; upk(lg0, lg1, lgP);
        lg0 += __shfl_xor_sync(0xffffffffu, lg0, 1);
        lg0 += __shfl_xor_sync(0xffffffffu, lg0, 2);
        lg1 += __shfl_xor_sync(0xffffffffu, lg1, 1);
        lg1 += __shfl_xor_sync(0xffffffffu, lg1, 2);

        if (tq == 0) {
            out[rg]  = __fdividef(1.0f, 1.0f + __expf(-(lg0 + cb)));
            out[rg8] = __fdividef(1.0f, 1.0f + __expf(-(lg1 + cb)));
        }
    }
}

extern "C" void kernel_launch(void* const* d_in, const int* in_sizes, int n_in,
                              void* d_out, int out_size) {
    const float* X      = (const float*)d_in[0];
    const float* Wih_b  = (const float*)d_in[7];
    const float* Wix_w  = (const float*)d_in[8];
    const float* Wix_b  = (const float*)d_in[9];
    const float* bi     = (const float*)d_in[10];
    const float* WTh_b  = (const float*)d_in[12];
    const float* WTx_w  = (const float*)d_in[13];
    const float* WTx_b  = (const float*)d_in[14];
    const float* WTt_w  = (const float*)d_in[15];
    const float* WTt_b  = (const float*)d_in[16];
    const float* bT     = (const float*)d_in[17];
    const float* cls_w  = (const float*)d_in[18];
    const float* cls_b  = (const float*)d_in[19];

    const int nrows  = in_sizes[0] / 15;
    const int blocks = nrows / 256;      // 4 warps/CTA x 64 rows/warp

    stgn_kernel<<<blocks, 128>>>(
        X, Wix_w, Wix_b, Wih_b, bi,
        WTx_w, WTx_b, WTh_b, WTt_w, WTt_b, bT,
        cls_w, cls_b, (float*)d_out);
}

// round 16
// speedup vs baseline: 1.2280x; 1.2280x over previous
#include <cuda_runtime.h>
#include <cstdint>
#include <math.h>

// ---------------------------------------------------------------------------
// STGN_LSTM == pointwise map of X[:,4,:].
// r15 lesson: cross-pipe offloads lose when glue >= savings (MMA regressed).
// r16 = r13 champion + exact-algebra cuts:
//  * cls_w folded into h-poly coefficients (A0w,A1w,A2w in table):
//      lg += m*(A0w + A1w*sm + A2w*sm^2)   -> -1 FMA2/row/pair
//  * 4 rows/thread: table LDS amortized 2 -> 1.25 per row; 4 independent
//    chains per pair batch MUFU issue (slack = MUFU latency exposure).
// Per row/pair: 18 FMA2 + 4 MUFU + 4 ALU + 1.25 LDS.
// ---------------------------------------------------------------------------

typedef unsigned long long u64;

static __device__ __forceinline__ float tanh_mufu(float x) {
    float y; asm("tanh.approx.f32 %0, %1;" : "=f"(y) : "f"(x)); return y;
}
static __device__ __forceinline__ u64 pk(float lo, float hi) {
    u64 r; asm("mov.b64 %0, {%1, %2};" : "=l"(r) : "f"(lo), "f"(hi)); return r;
}
static __device__ __forceinline__ void upk(float& lo, float& hi, u64 v) {
    asm("mov.b64 {%0, %1}, %2;" : "=f"(lo), "=f"(hi) : "l"(v));
}
static __device__ __forceinline__ u64 fma2(u64 a, u64 b, u64 c) {
    u64 d; asm("fma.rn.f32x2 %0, %1, %2, %3;" : "=l"(d) : "l"(a), "l"(b), "l"(c));
    return d;
}
static __device__ __forceinline__ u64 mul2(u64 a, u64 b) {
    u64 d; asm("mul.rn.f32x2 %0, %1, %2;" : "=l"(d) : "l"(a), "l"(b)); return d;
}
static __device__ __forceinline__ u64 tanh2_mufu(u64 v) {
    float a, b; upk(a, b, v);
    return pk(tanh_mufu(a), tanh_mufu(b));
}
static __device__ __forceinline__ u64 clamp2_pm2(u64 v) {
    float a, b; upk(a, b, v);
    a = fminf(fmaxf(a, -2.0f), 2.0f);
    b = fminf(fmaxf(b, -2.0f), 2.0f);
    return pk(a, b);
}

#define RPT 4   // rows per thread

__global__ void __launch_bounds__(128)
stgn_kernel(const float* __restrict__ X,
            const float* __restrict__ Wix, const float* __restrict__ Wix_b,
            const float* __restrict__ Wih_b, const float* __restrict__ bi,
            const float* __restrict__ WTx, const float* __restrict__ WTx_b,
            const float* __restrict__ WTh_b,
            const float* __restrict__ WTt, const float* __restrict__ WTt_b,
            const float* __restrict__ bT,
            const float* __restrict__ clsw, const float* __restrict__ clsb,
            float* __restrict__ out) {
    __shared__ alignas(16) float Tb[32 * 20 + 8];   // 20 floats (5 u64) / pair

    const int tid = threadIdx.x;

    // ---- table: per unit-pair, lanes = the two units ----
    if (tid < 64) {
        const int n = tid;
        const int p = n >> 1, e = n & 1;
        float* d = Tb + p * 20;
        const float w = clsw[n];
        d[0 + e]  = 0.5f * Wix[2 * n];                               // A
        d[2 + e]  = 0.5f * Wix[2 * n + 1];                           // B
        d[4 + e]  = 0.5f * (Wih_b[n] + Wix_b[n] + bi[n]);            // C
        d[6 + e]  = 0.5f * WTt[n];                                   // D
        d[8 + e]  = 0.5f * WTx[2 * n];                               // E
        d[10 + e] = 0.5f * WTx[2 * n + 1];                           // F
        d[12 + e] = 0.5f * (WTh_b[n] + WTx_b[n] + WTt_b[n] + bT[n]); // G
        d[14 + e] = 0.4997350f * w;                                  // A0*w
        d[16 + e] = -0.0397625f * w;                                 // A1*w
        d[18 + e] = 0.0025309f * w;                                  // A2*w
    }
    if (tid == 64) Tb[644] = clsb[0];
    __syncthreads();

    // ---- 4 rows/thread, coalesced at 4 offsets ----
    const size_t base = (size_t)blockIdx.x * (128 * RPT);
    size_t rows[RPT];
    u64 x0p[RPT], x1p[RPT], dtp[RPT], dhp[RPT], lg[RPT];
#pragma unroll
    for (int r = 0; r < RPT; r++) {
        rows[r] = base + (size_t)(r * 128 + tid);
        const float* xr = X + rows[r] * 15 + 12;
        const float x0 = xr[0], x1 = xr[1], dt = xr[2];
        x0p[r] = pk(x0, x0);
        x1p[r] = pk(x1, x1);
        dtp[r] = pk(dt, dt);
        dhp[r] = pk(0.5f * dt, 0.5f * dt);
        lg[r]  = pk(0.0f, 0.0f);
    }

    // t1 = z*P(z^2), z = clamp(0.5*zi, +-2), s in [0,4]
    const u64 C0 = pk(0.998779f, 0.998779f);
    const u64 C1 = pk(-0.3172255f, -0.3172255f);
    const u64 C2 = pk(0.096472f, 0.096472f);
    const u64 C3 = pk(-0.0181456f, -0.0181456f);
    const u64 C4 = pk(0.0014467f, 0.0014467f);

    const ulonglong2* TbV = (const ulonglong2*)Tb;

#pragma unroll
    for (int p = 0; p < 32; p++) {
        // 5 LDS.128: (A,B) (C,D) (E,F) (G,A0w) (A1w,A2w)
        const ulonglong2 v0 = TbV[5 * p + 0];
        const ulonglong2 v1 = TbV[5 * p + 1];
        const ulonglong2 v2 = TbV[5 * p + 2];
        const ulonglong2 v3 = TbV[5 * p + 3];
        const ulonglong2 v4 = TbV[5 * p + 4];

#pragma unroll
        for (int r = 0; r < RPT; r++) {
            const u64 z2 = fma2(v2.x, x0p[r],
                           fma2(v2.y, x1p[r], fma2(v1.y, dtp[r], v3.x)));   // 0.5*zT
            const u64 t2 = tanh2_mufu(z2);                                  // MUFU
            const u64 z1 = fma2(v0.x, x0p[r], fma2(v0.y, x1p[r], v1.x));    // 0.5*zi
            const u64 zc = clamp2_pm2(z1);                                  // ALU
            const u64 sz = mul2(zc, zc);
            u64 pq = fma2(C4, sz, C3);
            pq = fma2(pq, sz, C2);
            pq = fma2(pq, sz, C1);
            pq = fma2(pq, sz, C0);
            const u64 t1 = mul2(pq, zc);                // tanh(0.5*zi) on FMA
            const u64 ta = fma2(t2, dhp[r], dhp[r]);    // sig(zT)*dt
            const u64 uu = tanh2_mufu(ta);              // MUFU
            const u64 m  = fma2(t1, uu, uu);            // 2*cc, |m|<=2
            const u64 sm = mul2(m, m);
            u64 q = fma2(v4.y, sm, v4.x);               // A2w*sm + A1w
            q = fma2(q, sm, v3.y);                      // ... + A0w
            lg[r] = fma2(q, m, lg[r]);                  // += w*h
        }
    }

    const float cb = Tb[644];
#pragma unroll
    for (int r = 0; r < RPT; r++) {
        float a0, a1; upk(a0, a1, lg[r]);
        out[rows[r]] = __fdividef(1.0f, 1.0f + __expf(-(a0 + a1 + cb)));
    }
}

extern "C" void kernel_launch(void* const* d_in, const int* in_sizes, int n_in,
                              void* d_out, int out_size) {
    const float* X      = (const float*)d_in[0];
    const float* Wih_b  = (const float*)d_in[7];
    const float* Wix_w  = (const float*)d_in[8];
    const float* Wix_b  = (const float*)d_in[9];
    const float* bi     = (const float*)d_in[10];
    const float* WTh_b  = (const float*)d_in[12];
    const float* WTx_w  = (const float*)d_in[13];
    const float* WTx_b  = (const float*)d_in[14];
    const float* WTt_w  = (const float*)d_in[15];
    const float* WTt_b  = (const float*)d_in[16];
    const float* bT     = (const float*)d_in[17];
    const float* cls_w  = (const float*)d_in[18];
    const float* cls_b  = (const float*)d_in[19];

    const int nrows  = in_sizes[0] / 15;
    const int blocks = nrows / (128 * RPT);   // 1024 CTAs

    stgn_kernel<<<blocks, 128>>>(
        X, Wix_w, Wix_b, Wih_b, bi,
        WTx_w, WTx_b, WTh_b, WTt_w, WTt_b, bT,
        cls_w, cls_b, (float*)d_out);
}

// round 17
// speedup vs baseline: 1.2912x; 1.0515x over previous
#include <cuda_runtime.h>
#include <cstdint>
#include <math.h>

// ---------------------------------------------------------------------------
// STGN_LSTM == pointwise map of X[:,4,:].
// r17 = r13 champion shape (2 rows/thread, ~40 regs, occ ~51%) + cls_w folded
// into the h-poly coefficients (exact algebra):
//   lg += m*(A0w + A1w*sm + A2w*sm^2)   [one fma2 fewer per row per pair]
// Per row/pair: 16 FMA2 + 4 MUFU + 4 ALU + 1.25 LDS.
// r16 lesson: 4 rows/thread (72 regs, occ 35%) regressed -> stay at 2.
// ---------------------------------------------------------------------------

typedef unsigned long long u64;

static __device__ __forceinline__ float tanh_mufu(float x) {
    float y; asm("tanh.approx.f32 %0, %1;" : "=f"(y) : "f"(x)); return y;
}
static __device__ __forceinline__ u64 pk(float lo, float hi) {
    u64 r; asm("mov.b64 %0, {%1, %2};" : "=l"(r) : "f"(lo), "f"(hi)); return r;
}
static __device__ __forceinline__ void upk(float& lo, float& hi, u64 v) {
    asm("mov.b64 {%0, %1}, %2;" : "=f"(lo), "=f"(hi) : "l"(v));
}
static __device__ __forceinline__ u64 fma2(u64 a, u64 b, u64 c) {
    u64 d; asm("fma.rn.f32x2 %0, %1, %2, %3;" : "=l"(d) : "l"(a), "l"(b), "l"(c));
    return d;
}
static __device__ __forceinline__ u64 mul2(u64 a, u64 b) {
    u64 d; asm("mul.rn.f32x2 %0, %1, %2;" : "=l"(d) : "l"(a), "l"(b)); return d;
}
static __device__ __forceinline__ u64 tanh2_mufu(u64 v) {
    float a, b; upk(a, b, v);
    return pk(tanh_mufu(a), tanh_mufu(b));
}
static __device__ __forceinline__ u64 clamp2_pm2(u64 v) {
    float a, b; upk(a, b, v);
    a = fminf(fmaxf(a, -2.0f), 2.0f);
    b = fminf(fmaxf(b, -2.0f), 2.0f);
    return pk(a, b);
}

__global__ void __launch_bounds__(128)
stgn_kernel(const float* __restrict__ X,
            const float* __restrict__ Wix, const float* __restrict__ Wix_b,
            const float* __restrict__ Wih_b, const float* __restrict__ bi,
            const float* __restrict__ WTx, const float* __restrict__ WTx_b,
            const float* __restrict__ WTh_b,
            const float* __restrict__ WTt, const float* __restrict__ WTt_b,
            const float* __restrict__ bT,
            const float* __restrict__ clsw, const float* __restrict__ clsb,
            float* __restrict__ out) {
    __shared__ alignas(16) float Tb[32 * 20 + 8];   // 5 u64 per unit-pair

    const int tid = threadIdx.x;

    // ---- table: per unit-pair, lanes = the two units ----
    if (tid < 64) {
        const int n = tid;
        const int p = n >> 1, e = n & 1;
        float* d = Tb + p * 20;
        const float w = clsw[n];
        d[0 + e]  = 0.5f * Wix[2 * n];                               // A
        d[2 + e]  = 0.5f * Wix[2 * n + 1];                           // B
        d[4 + e]  = 0.5f * (Wih_b[n] + Wix_b[n] + bi[n]);            // C
        d[6 + e]  = 0.5f * WTt[n];                                   // D
        d[8 + e]  = 0.5f * WTx[2 * n];                               // E
        d[10 + e] = 0.5f * WTx[2 * n + 1];                           // F
        d[12 + e] = 0.5f * (WTh_b[n] + WTx_b[n] + WTt_b[n] + bT[n]); // G
        d[14 + e] = 0.4997350f * w;                                  // A0*w
        d[16 + e] = -0.0397625f * w;                                 // A1*w
        d[18 + e] = 0.0025309f * w;                                  // A2*w
    }
    if (tid == 64) Tb[644] = clsb[0];
    __syncthreads();

    // ---- two rows per thread: r0 = base+tid, r1 = r0+128 (coalesced) ----
    const size_t base = (size_t)blockIdx.x * 256;
    const size_t r0 = base + tid;
    const size_t r1 = r0 + 128;

    const float* xa = X + r0 * 15 + 12;
    const float* xb = X + r1 * 15 + 12;
    const float x0a = xa[0], x1a = xa[1], dta = xa[2];
    const float x0b = xb[0], x1b = xb[1], dtb = xb[2];

    const u64 x0A = pk(x0a, x0a), x1A = pk(x1a, x1a);
    const u64 dtA = pk(dta, dta), dhA = pk(0.5f * dta, 0.5f * dta);
    const u64 x0B = pk(x0b, x0b), x1B = pk(x1b, x1b);
    const u64 dtB = pk(dtb, dtb), dhB = pk(0.5f * dtb, 0.5f * dtb);

    // t1 = z*P(z^2), z = clamp(0.5*zi, +-2), s in [0,4]
    const u64 C0 = pk(0.998779f, 0.998779f);
    const u64 C1 = pk(-0.3172255f, -0.3172255f);
    const u64 C2 = pk(0.096472f, 0.096472f);
    const u64 C3 = pk(-0.0181456f, -0.0181456f);
    const u64 C4 = pk(0.0014467f, 0.0014467f);

    u64 lgA = pk(0.0f, 0.0f);
    u64 lgB = pk(0.0f, 0.0f);

    const ulonglong2* TbV = (const ulonglong2*)Tb;

#pragma unroll
    for (int p = 0; p < 32; p++) {
        // 5 LDS.128: (A,B) (C,D) (E,F) (G,A0w) (A1w,A2w)
        const ulonglong2 v0 = TbV[5 * p + 0];
        const ulonglong2 v1 = TbV[5 * p + 1];
        const ulonglong2 v2 = TbV[5 * p + 2];
        const ulonglong2 v3 = TbV[5 * p + 3];
        const ulonglong2 v4 = TbV[5 * p + 4];

        // ---- row A ----
        {
            const u64 z2 = fma2(v2.x, x0A, fma2(v2.y, x1A, fma2(v1.y, dtA, v3.x))); // 0.5*zT
            const u64 t2 = tanh2_mufu(z2);                                          // MUFU
            const u64 z1 = fma2(v0.x, x0A, fma2(v0.y, x1A, v1.x));                  // 0.5*zi
            const u64 zc = clamp2_pm2(z1);                                          // ALU
            const u64 sz = mul2(zc, zc);
            u64 pq = fma2(C4, sz, C3);
            pq = fma2(pq, sz, C2);
            pq = fma2(pq, sz, C1);
            pq = fma2(pq, sz, C0);
            const u64 t1 = mul2(pq, zc);                // tanh(0.5*zi) on FMA
            const u64 ta = fma2(t2, dhA, dhA);          // sig(zT)*dt
            const u64 uu = tanh2_mufu(ta);              // MUFU
            const u64 m  = fma2(t1, uu, uu);            // 2*cc, |m|<=2
            const u64 sm = mul2(m, m);
            u64 q = fma2(v4.y, sm, v4.x);               // A2w*sm + A1w
            q = fma2(q, sm, v3.y);                      // ... + A0w
            lgA = fma2(q, m, lgA);                      // += w*h
        }
        // ---- row B ----
        {
            const u64 z2 = fma2(v2.x, x0B, fma2(v2.y, x1B, fma2(v1.y, dtB, v3.x)));
            const u64 t2 = tanh2_mufu(z2);
            const u64 z1 = fma2(v0.x, x0B, fma2(v0.y, x1B, v1.x));
            const u64 zc = clamp2_pm2(z1);
            const u64 sz = mul2(zc, zc);
            u64 pq = fma2(C4, sz, C3);
            pq = fma2(pq, sz, C2);
            pq = fma2(pq, sz, C1);
            pq = fma2(pq, sz, C0);
            const u64 t1 = mul2(pq, zc);
            const u64 ta = fma2(t2, dhB, dhB);
            const u64 uu = tanh2_mufu(ta);
            const u64 m  = fma2(t1, uu, uu);
            const u64 sm = mul2(m, m);
            u64 q = fma2(v4.y, sm, v4.x);
            q = fma2(q, sm, v3.y);
            lgB = fma2(q, m, lgB);
        }
    }

    const float cb = Tb[644];
    float a0, a1, b0, b1;
    upk(a0, a1, lgA);
    upk(b0, b1, lgB);
    out[r0] = __fdividef(1.0f, 1.0f + __expf(-(a0 + a1 + cb)));
    out[r1] = __fdividef(1.0f, 1.0f + __expf(-(b0 + b1 + cb)));
}

extern "C" void kernel_launch(void* const* d_in, const int* in_sizes, int n_in,
                              void* d_out, int out_size) {
    const float* X      = (const float*)d_in[0];
    const float* Wih_b  = (const float*)d_in[7];
    const float* Wix_w  = (const float*)d_in[8];
    const float* Wix_b  = (const float*)d_in[9];
    const float* bi     = (const float*)d_in[10];
    const float* WTh_b  = (const float*)d_in[12];
    const float* WTx_w  = (const float*)d_in[13];
    const float* WTx_b  = (const float*)d_in[14];
    const float* WTt_w  = (const float*)d_in[15];
    const float* WTt_b  = (const float*)d_in[16];
    const float* bT     = (const float*)d_in[17];
    const float* cls_w  = (const float*)d_in[18];
    const float* cls_b  = (const float*)d_in[19];

    const int nrows  = in_sizes[0] / 15;
    const int blocks = nrows / 256;      // 2048 CTAs x 128 threads, 2 rows/thread

    stgn_kernel<<<blocks, 128>>>(
        X, Wix_w, Wix_b, Wih_b, bi,
        WTx_w, WTx_b, WTh_b, WTt_w, WTt_b, bT,
        cls_w, cls_b, (float*)d_out);
}